// round 16
// baseline (speedup 1.0000x reference)
#include <cuda_runtime.h>
#include <cuda_fp16.h>
#include <cstdint>

#define MM 256
#define OO 8192
#define II 8192
#define NNZ_TOTAL 3350528
#define NBUCKET 256          // 32-wide k buckets
#define NITER 64             // II / 128
#define A_BYTES 65536        // 256 rows x 128k fp16 (two 32KB k-halves)
#define B_BYTES 16384        // 64 rows x 128k fp16 (two 8KB k-halves)
#define STAGE_BYTES (A_BYTES + B_BYTES)     // 81920
#define SMEM_BYTES (2 * STAGE_BYTES)        // 163840

__device__ __half         g_xh[MM * II];
__device__ unsigned short g_rk[NNZ_TOTAL];
__device__ __half         g_rv[NNZ_TOTAL];
__device__ int            g_roff[OO * (NBUCKET + 1)];

__device__ __forceinline__ uint32_t smem_u32(const void* p) {
    uint32_t a;
    asm("{ .reg .u64 t; cvta.to.shared.u64 t, %1; cvt.u32.u64 %0, t; }" : "=r"(a) : "l"(p));
    return a;
}
__device__ __forceinline__ uint32_t sw(uint32_t off) { return off ^ ((off >> 3) & 0x70u); }
// one packed int32 holds ONE byte: low nibble -> even k, high nibble -> odd k; (value-8) exact in f16
__device__ __forceinline__ uint32_t dq(uint32_t v) {
    uint32_t h = 0x64006400u | (v & 0xFu) | ((v << 12) & 0x000F0000u);
    __half2 a = *reinterpret_cast<__half2*>(&h);
    uint32_t c8 = 0x64086408u;
    __half2 b = *reinterpret_cast<__half2*>(&c8);
    __half2 r = __hsub2(a, b);
    return *reinterpret_cast<uint32_t*>(&r);
}

// fused prep: blocks [0,2048) convert x fp32->fp16; blocks [2048,10240) sort residuals
// (dtype sniff inlined per residual block: 256B read, L2-broadcast, ~free)
__global__ void prep_kernel(const float* __restrict__ x,
                            const void* __restrict__ vals, const int* __restrict__ idx,
                            const int* __restrict__ ptr, const float* __restrict__ scales,
                            const float* __restrict__ alphap) {
    if (blockIdx.x < 2048) {
        int i = blockIdx.x * 256 + threadIdx.x;
        float4 v = reinterpret_cast<const float4*>(x)[i];
        reinterpret_cast<__half2*>(g_xh)[i * 2 + 0] = __floats2half2_rn(v.x, v.y);
        reinterpret_cast<__half2*>(g_xh)[i * 2 + 1] = __floats2half2_rn(v.z, v.w);
        return;
    }
    __shared__ int cnt[NBUCKET], run[NBUCKET], pref[NBUCKET + 1];
    __shared__ int a16, abf;
    const int o = blockIdx.x - 2048, t = threadIdx.x;
    const int s = ptr[o], e = ptr[o + 1], n = e - s;
    cnt[t] = 0; run[t] = 0;
    if (t == 0) { a16 = 1; abf = 1; }
    __syncthreads();
    {   // inline dtype sniff on first 128 u16 of vals
        unsigned short u = reinterpret_cast<const unsigned short*>(vals)[t & 127];
        float h = __half2float(__ushort_as_half(u));
        float b = __uint_as_float(((uint32_t)u) << 16);
        if (!(fabsf(h) < 0.5f)) atomicAnd(&a16, 0);
        if (!(fabsf(b) < 0.5f)) atomicAnd(&abf, 0);
    }
    for (int j = t; j < n; j += 256) atomicAdd(&cnt[idx[s + j] >> 5], 1);
    __syncthreads();
    const int mode = a16 ? 0 : (abf ? 1 : 2);
    if (t == 0) { int a = 0; for (int c = 0; c < NBUCKET; c++) { pref[c] = a; a += cnt[c]; } pref[NBUCKET] = a; }
    __syncthreads();
    g_roff[o * (NBUCKET + 1) + t] = s + pref[t];
    if (t == 0) g_roff[o * (NBUCKET + 1) + NBUCKET] = s + pref[NBUCKET];
    const float inv = alphap[0] / scales[o];
    for (int j = t; j < n; j += 256) {
        const int k = idx[s + j];
        const int pos = s + pref[k >> 5] + atomicAdd(&run[k >> 5], 1);
        float v;
        if (mode == 0)      v = __half2float(reinterpret_cast<const __half*>(vals)[s + j]);
        else if (mode == 1) v = __uint_as_float(((uint32_t)reinterpret_cast<const unsigned short*>(vals)[s + j]) << 16);
        else                v = reinterpret_cast<const float*>(vals)[s + j];
        g_rk[pos] = (unsigned short)k;
        g_rv[pos] = __float2half_rn(v * inv);
    }
}

// ---- fused dequant GEMM: out[256,8192] = x @ W^T ----
// CTA tile m=256 (ALL M) x o=64 (dequant-once), K chunks 128, 2 stages,
// 512 threads, warp tile 32x32 (8m x 2n). Inner loop: kk-PAIR fragment
// batching + per-warp phase rotation to break LDSM->HMMA stall alignment.
__device__ __forceinline__ void cpa_A(uint32_t Ab, int k0, int tid) {
#pragma unroll
    for (int r = 0; r < 8; r++) {
        const int u = tid + r * 512, row = u >> 4, seg = u & 15;
        const __half* src = g_xh + (size_t)row * II + k0 + seg * 8;
        uint32_t off = ((uint32_t)(seg >> 3) << 15) + (uint32_t)(row * 128 + (seg & 7) * 16);
        asm volatile("cp.async.cg.shared.global [%0], [%1], 16;" :: "r"(Ab + sw(off)), "l"(src));
    }
    asm volatile("cp.async.commit_group;" ::: "memory");
}
// B: threads 0..255 own (row = tid>>2 in 0..63, 32-k window = tid&3)
__device__ __forceinline__ void ldg_B(const int* __restrict__ packed, int o_base, int k0, int tid, uint4* pk) {
    if (tid >= 256) return;
    const int row = tid >> 2, seg = tid & 3;
    const uint4* src = reinterpret_cast<const uint4*>(
        packed + (size_t)(o_base + row) * (II / 2) + (k0 >> 1) + seg * 16);
#pragma unroll
    for (int j = 0; j < 4; j++) pk[j] = src[j];
}
__device__ __forceinline__ void sts_fold_B(uint32_t Bb, const uint4* pk, int o_base, int k0, int tid) {
    if (tid >= 256) return;
    const int row = tid >> 2, seg = tid & 3;
    const uint32_t hb = ((uint32_t)(seg >> 1) << 13) + (uint32_t)(row * 128 + (seg & 1) * 64);
#pragma unroll
    for (int j = 0; j < 4; j++) {
        uint32_t ad = Bb + sw(hb + j * 16);
        asm volatile("st.shared.v4.b32 [%0], {%1,%2,%3,%4};"
                     :: "r"(ad), "r"(dq(pk[j].x)), "r"(dq(pk[j].y)), "r"(dq(pk[j].z)), "r"(dq(pk[j].w)) : "memory");
    }
    // residual fold: same thread owns this (row, 32-k) window -> program-order safe
    const int o = o_base + row;
    const int b = (k0 >> 5) + seg;
    const int s0 = g_roff[o * (NBUCKET + 1) + b];
    const int s1 = g_roff[o * (NBUCKET + 1) + b + 1];
    const int kb = k0 + seg * 32;
    for (int j = s0; j < s1; j++) {
        const int kl = (int)g_rk[j] - kb;
        uint32_t ad = Bb + sw(hb + (uint32_t)(kl * 2));
        unsigned short u16;
        asm volatile("ld.shared.b16 %0, [%1];" : "=h"(u16) : "r"(ad));
        __half v = __hadd(__ushort_as_half(u16), g_rv[j]);
        u16 = __half_as_ushort(v);
        asm volatile("st.shared.b16 [%0], %1;" :: "r"(ad), "h"(u16) : "memory");
    }
}

__global__ void __launch_bounds__(512, 1)
gemm_kernel(const int* __restrict__ packed, const float* __restrict__ scales, float* __restrict__ out) {
    extern __shared__ char smem[];
    const uint32_t sb = smem_u32(smem);
    const int tid = threadIdx.x, wid = tid >> 5, lane = tid & 31;
    const int wm = wid >> 1, wn = wid & 1;                 // 8m x 2n warps, warp tile 32x32
    const int o_base = blockIdx.x * 64;
    const int rot = wid & 3;                               // per-warp kk-pair phase rotation

    float c[2][4][4];
#pragma unroll
    for (int mt = 0; mt < 2; mt++)
#pragma unroll
        for (int nt = 0; nt < 4; nt++)
#pragma unroll
            for (int q = 0; q < 4; q++) c[mt][nt][q] = 0.f;

    // prologue: fill stage 0
    {
        cpa_A(sb, 0, tid);                                  // commits g0
        uint4 pk[4];
        ldg_B(packed, o_base, 0, tid, pk);
        sts_fold_B(sb + A_BYTES, pk, o_base, 0, tid);
    }

    for (int ch = 0; ch < NITER; ch++) {
        const uint32_t cur = sb + (uint32_t)(ch & 1) * STAGE_BYTES;
        uint4 pk[4];
        const bool produce = (ch + 1) < NITER;
        const int pch = ch + 1;
        const uint32_t pbase = sb + (uint32_t)(pch & 1) * STAGE_BYTES;

        // pre-barrier: B LDGs for next chunk (register-only) gain the convoy time as DRAM cover
        if (produce) ldg_B(packed, o_base, pch * 128, tid, pk);

        asm volatile("cp.async.wait_group 0;" ::: "memory");   // stage ch's A complete
        __syncthreads();   // stage ch visible; all warps done with stage ch-1 -> reusable

        if (produce) cpa_A(pbase, pch * 128, tid);             // fills other stage during compute

        // compute: 4 kk-pairs, rotated per warp; fragments for both kk of a pair
        // loaded before any MMA -> one stall window per 16 MMAs
#pragma unroll
        for (int pp = 0; pp < 4; pp++) {
            const int p = (pp + rot) & 3;                      // pair index 0..3 -> kk {2p, 2p+1}
            uint32_t a[2][2][4], b[2][4][2];
#pragma unroll
            for (int hf = 0; hf < 2; hf++) {
                const int kk = 2 * p + hf;
                const uint32_t akh = ((uint32_t)(kk >> 2) << 15);
                const uint32_t bkh = ((uint32_t)(kk >> 2) << 13);
                const int kkl = kk & 3;
#pragma unroll
                for (int mt = 0; mt < 2; mt++) {
                    const int row = wm * 32 + mt * 16 + (lane & 15);
                    uint32_t ad = cur + sw(akh + (uint32_t)(row * 128 + kkl * 32 + (lane >> 4) * 16));
                    asm volatile("ldmatrix.sync.aligned.m8n8.x4.shared.b16 {%0,%1,%2,%3}, [%4];"
                                 : "=r"(a[hf][mt][0]), "=r"(a[hf][mt][1]),
                                   "=r"(a[hf][mt][2]), "=r"(a[hf][mt][3]) : "r"(ad));
                }
#pragma unroll
                for (int ntp = 0; ntp < 2; ntp++) {
                    const int row = wn * 32 + ntp * 16 + ((lane >> 4) & 1) * 8 + (lane & 7);
                    uint32_t ad = cur + A_BYTES + sw(bkh + (uint32_t)(row * 128 + kkl * 32 + ((lane >> 3) & 1) * 16));
                    asm volatile("ldmatrix.sync.aligned.m8n8.x4.shared.b16 {%0,%1,%2,%3}, [%4];"
                                 : "=r"(b[hf][2 * ntp][0]), "=r"(b[hf][2 * ntp][1]),
                                   "=r"(b[hf][2 * ntp + 1][0]), "=r"(b[hf][2 * ntp + 1][1]) : "r"(ad));
                }
            }
#pragma unroll
            for (int hf = 0; hf < 2; hf++)
#pragma unroll
                for (int mt = 0; mt < 2; mt++)
#pragma unroll
                    for (int nt = 0; nt < 4; nt++)
                        asm volatile("mma.sync.aligned.m16n8k16.row.col.f32.f16.f16.f32 "
                                     "{%0,%1,%2,%3}, {%4,%5,%6,%7}, {%8,%9}, {%0,%1,%2,%3};"
                                     : "+f"(c[mt][nt][0]), "+f"(c[mt][nt][1]), "+f"(c[mt][nt][2]), "+f"(c[mt][nt][3])
                                     : "r"(a[hf][mt][0]), "r"(a[hf][mt][1]), "r"(a[hf][mt][2]), "r"(a[hf][mt][3]),
                                       "r"(b[hf][nt][0]), "r"(b[hf][nt][1]));
        }

        if (produce)
            sts_fold_B(pbase + A_BYTES, pk, o_base, pch * 128, tid);  // own stores; visible via next bar
    }

    // epilogue: per-o scale in fp32, direct float2 stores
#pragma unroll
    for (int mt = 0; mt < 2; mt++) {
        const int m0 = wm * 32 + mt * 16 + (lane >> 2);
#pragma unroll
        for (int nt = 0; nt < 4; nt++) {
            const int o = o_base + wn * 32 + nt * 8 + (lane & 3) * 2;
            const float2 s = *reinterpret_cast<const float2*>(scales + o);
            float2 r0, r1;
            r0.x = c[mt][nt][0] * s.x; r0.y = c[mt][nt][1] * s.y;
            r1.x = c[mt][nt][2] * s.x; r1.y = c[mt][nt][3] * s.y;
            *reinterpret_cast<float2*>(out + (size_t)m0 * OO + o) = r0;
            *reinterpret_cast<float2*>(out + (size_t)(m0 + 8) * OO + o) = r1;
        }
    }
}

extern "C" void kernel_launch(void* const* d_in, const int* in_sizes, int n_in,
                              void* d_out, int out_size) {
    const float* x      = (const float*)d_in[0];
    const int*   packed = (const int*)d_in[1];
    const float* scales = (const float*)d_in[2];
    const void*  vals   = (const void*)d_in[3];
    const int*   idx    = (const int*)d_in[4];
    const int*   ptr    = (const int*)d_in[5];
    const float* alpha  = (const float*)d_in[6];
    float* out = (float*)d_out;

    cudaFuncSetAttribute(gemm_kernel, cudaFuncAttributeMaxDynamicSharedMemorySize, SMEM_BYTES);
    prep_kernel<<<2048 + OO, 256>>>(x, vals, idx, ptr, scales, alpha);
    gemm_kernel<<<128, 512, SMEM_BYTES>>>(packed, scales, out);
}

// round 17
// speedup vs baseline: 1.1287x; 1.1287x over previous
#include <cuda_runtime.h>
#include <cuda_fp16.h>
#include <cstdint>

#define MM 256
#define OO 8192
#define II 8192
#define NNZ_TOTAL 3350528
#define NBUCKET 256          // 32-wide k buckets
#define NITER 64             // II / 128
#define A_BYTES 65536        // 256 rows x 128k fp16 (two 32KB k-halves)
#define B_BYTES 16384        // 64 rows x 128k fp16 (two 8KB k-halves)
#define STAGE_BYTES (A_BYTES + B_BYTES)     // 81920
#define SMEM_BYTES (2 * STAGE_BYTES)        // 163840

__device__ __half         g_xh[MM * II];
__device__ unsigned short g_rk[NNZ_TOTAL];
__device__ __half         g_rv[NNZ_TOTAL];
__device__ int            g_roff[OO * (NBUCKET + 1)];
__device__ int            g_mode;   // 0=f16, 1=bf16, 2=f32

__device__ __forceinline__ uint32_t smem_u32(const void* p) {
    uint32_t a;
    asm("{ .reg .u64 t; cvta.to.shared.u64 t, %1; cvt.u32.u64 %0, t; }" : "=r"(a) : "l"(p));
    return a;
}
__device__ __forceinline__ uint32_t sw(uint32_t off) { return off ^ ((off >> 3) & 0x70u); }
// one packed int32 holds ONE byte: low nibble -> even k, high nibble -> odd k; (value-8) exact in f16
__device__ __forceinline__ uint32_t dq(uint32_t v) {
    uint32_t h = 0x64006400u | (v & 0xFu) | ((v << 12) & 0x000F0000u);
    __half2 a = *reinterpret_cast<__half2*>(&h);
    uint32_t c8 = 0x64086408u;
    __half2 b = *reinterpret_cast<__half2*>(&c8);
    __half2 r = __hsub2(a, b);
    return *reinterpret_cast<uint32_t*>(&r);
}

// parallel dtype sniff (separate tiny kernel: 4.3us measured)
__global__ void sniff_vals(const unsigned short* __restrict__ p) {
    __shared__ int a16, abf;
    const int t = threadIdx.x;   // 128 threads
    if (t == 0) { a16 = 1; abf = 1; }
    __syncthreads();
    unsigned short u = p[t];
    float h = __half2float(__ushort_as_half(u));
    float b = __uint_as_float(((uint32_t)u) << 16);
    if (!(fabsf(h) < 0.5f)) atomicAnd(&a16, 0);
    if (!(fabsf(b) < 0.5f)) atomicAnd(&abf, 0);
    __syncthreads();
    if (t == 0) g_mode = a16 ? 0 : (abf ? 1 : 2);
}

// fused prep: blocks [0,2048) convert x fp32->fp16; blocks [2048,10240) sort residuals.
// Bucket prefix sum via Hillis-Steele parallel scan (was thread-0 serial loop).
__global__ void prep_kernel(const float* __restrict__ x,
                            const void* __restrict__ vals, const int* __restrict__ idx,
                            const int* __restrict__ ptr, const float* __restrict__ scales,
                            const float* __restrict__ alphap) {
    if (blockIdx.x < 2048) {
        int i = blockIdx.x * 256 + threadIdx.x;
        float4 v = reinterpret_cast<const float4*>(x)[i];
        reinterpret_cast<__half2*>(g_xh)[i * 2 + 0] = __floats2half2_rn(v.x, v.y);
        reinterpret_cast<__half2*>(g_xh)[i * 2 + 1] = __floats2half2_rn(v.z, v.w);
        return;
    }
    __shared__ int cnt[NBUCKET], run[NBUCKET], scan[NBUCKET];
    const int o = blockIdx.x - 2048, t = threadIdx.x;
    const int s = ptr[o], e = ptr[o + 1], n = e - s;
    const int mode = g_mode;
    cnt[t] = 0; run[t] = 0;
    __syncthreads();
    for (int j = t; j < n; j += 256) atomicAdd(&cnt[idx[s + j] >> 5], 1);
    __syncthreads();
    // Hillis-Steele inclusive scan over 256 buckets
    int v = cnt[t];
    scan[t] = v;
    __syncthreads();
#pragma unroll
    for (int off = 1; off < NBUCKET; off <<= 1) {
        int add = (t >= off) ? scan[t - off] : 0;
        __syncthreads();
        scan[t] += add;
        __syncthreads();
    }
    const int pref_ex = scan[t] - v;   // exclusive prefix
    g_roff[o * (NBUCKET + 1) + t] = s + pref_ex;
    if (t == 0) g_roff[o * (NBUCKET + 1) + NBUCKET] = s + scan[NBUCKET - 1];
    const float inv = alphap[0] / scales[o];
    __syncthreads();
    for (int j = t; j < n; j += 256) {
        const int k = idx[s + j];
        const int b = k >> 5;
        const int pos = s + (scan[b] - cnt[b]) + atomicAdd(&run[b], 1);
        float fv;
        if (mode == 0)      fv = __half2float(reinterpret_cast<const __half*>(vals)[s + j]);
        else if (mode == 1) fv = __uint_as_float(((uint32_t)reinterpret_cast<const unsigned short*>(vals)[s + j]) << 16);
        else                fv = reinterpret_cast<const float*>(vals)[s + j];
        g_rk[pos] = (unsigned short)k;
        g_rv[pos] = __float2half_rn(fv * inv);
    }
}

// ---- fused dequant GEMM: out[256,8192] = x @ W^T ----
// CTA tile m=256 (ALL M) x o=64 (dequant-once), K chunks 128, 2 stages,
// 512 threads, warp tile 32x32 (8m x 2n). Inner loop: kk-PAIR fragment
// batching + per-warp phase rotation (R16, ncu-verified 231us).
__device__ __forceinline__ void cpa_A(uint32_t Ab, int k0, int tid) {
#pragma unroll
    for (int r = 0; r < 8; r++) {
        const int u = tid + r * 512, row = u >> 4, seg = u & 15;
        const __half* src = g_xh + (size_t)row * II + k0 + seg * 8;
        uint32_t off = ((uint32_t)(seg >> 3) << 15) + (uint32_t)(row * 128 + (seg & 7) * 16);
        asm volatile("cp.async.cg.shared.global [%0], [%1], 16;" :: "r"(Ab + sw(off)), "l"(src));
    }
    asm volatile("cp.async.commit_group;" ::: "memory");
}
// B: threads 0..255 own (row = tid>>2 in 0..63, 32-k window = tid&3)
__device__ __forceinline__ void ldg_B(const int* __restrict__ packed, int o_base, int k0, int tid, uint4* pk) {
    if (tid >= 256) return;
    const int row = tid >> 2, seg = tid & 3;
    const uint4* src = reinterpret_cast<const uint4*>(
        packed + (size_t)(o_base + row) * (II / 2) + (k0 >> 1) + seg * 16);
#pragma unroll
    for (int j = 0; j < 4; j++) pk[j] = src[j];
}
__device__ __forceinline__ void sts_fold_B(uint32_t Bb, const uint4* pk, int o_base, int k0, int tid) {
    if (tid >= 256) return;
    const int row = tid >> 2, seg = tid & 3;
    const uint32_t hb = ((uint32_t)(seg >> 1) << 13) + (uint32_t)(row * 128 + (seg & 1) * 64);
#pragma unroll
    for (int j = 0; j < 4; j++) {
        uint32_t ad = Bb + sw(hb + j * 16);
        asm volatile("st.shared.v4.b32 [%0], {%1,%2,%3,%4};"
                     :: "r"(ad), "r"(dq(pk[j].x)), "r"(dq(pk[j].y)), "r"(dq(pk[j].z)), "r"(dq(pk[j].w)) : "memory");
    }
    // residual fold: same thread owns this (row, 32-k) window -> program-order safe
    const int o = o_base + row;
    const int b = (k0 >> 5) + seg;
    const int s0 = g_roff[o * (NBUCKET + 1) + b];
    const int s1 = g_roff[o * (NBUCKET + 1) + b + 1];
    const int kb = k0 + seg * 32;
    for (int j = s0; j < s1; j++) {
        const int kl = (int)g_rk[j] - kb;
        uint32_t ad = Bb + sw(hb + (uint32_t)(kl * 2));
        unsigned short u16;
        asm volatile("ld.shared.b16 %0, [%1];" : "=h"(u16) : "r"(ad));
        __half v = __hadd(__ushort_as_half(u16), g_rv[j]);
        u16 = __half_as_ushort(v);
        asm volatile("st.shared.b16 [%0], %1;" :: "r"(ad), "h"(u16) : "memory");
    }
}

__global__ void __launch_bounds__(512, 1)
gemm_kernel(const int* __restrict__ packed, const float* __restrict__ scales, float* __restrict__ out) {
    extern __shared__ char smem[];
    const uint32_t sb = smem_u32(smem);
    const int tid = threadIdx.x, wid = tid >> 5, lane = tid & 31;
    const int wm = wid >> 1, wn = wid & 1;                 // 8m x 2n warps, warp tile 32x32
    const int o_base = blockIdx.x * 64;
    const int rot = wid & 3;                               // per-warp kk-pair phase rotation

    float c[2][4][4];
#pragma unroll
    for (int mt = 0; mt < 2; mt++)
#pragma unroll
        for (int nt = 0; nt < 4; nt++)
#pragma unroll
            for (int q = 0; q < 4; q++) c[mt][nt][q] = 0.f;

    // prologue: fill stage 0
    {
        cpa_A(sb, 0, tid);                                  // commits g0
        uint4 pk[4];
        ldg_B(packed, o_base, 0, tid, pk);
        sts_fold_B(sb + A_BYTES, pk, o_base, 0, tid);
    }

    for (int ch = 0; ch < NITER; ch++) {
        const uint32_t cur = sb + (uint32_t)(ch & 1) * STAGE_BYTES;
        uint4 pk[4];
        const bool produce = (ch + 1) < NITER;
        const int pch = ch + 1;
        const uint32_t pbase = sb + (uint32_t)(pch & 1) * STAGE_BYTES;

        // pre-barrier: B LDGs for next chunk (register-only) gain the convoy time as DRAM cover
        if (produce) ldg_B(packed, o_base, pch * 128, tid, pk);

        asm volatile("cp.async.wait_group 0;" ::: "memory");   // stage ch's A complete
        __syncthreads();   // stage ch visible; all warps done with stage ch-1 -> reusable

        if (produce) cpa_A(pbase, pch * 128, tid);             // fills other stage during compute

        // compute: 4 kk-pairs, rotated per warp; fragments for both kk of a pair
        // loaded before any MMA -> one stall window per 16 MMAs
#pragma unroll
        for (int pp = 0; pp < 4; pp++) {
            const int p = (pp + rot) & 3;                      // pair index 0..3 -> kk {2p, 2p+1}
            uint32_t a[2][2][4], b[2][4][2];
#pragma unroll
            for (int hf = 0; hf < 2; hf++) {
                const int kk = 2 * p + hf;
                const uint32_t akh = ((uint32_t)(kk >> 2) << 15);
                const uint32_t bkh = ((uint32_t)(kk >> 2) << 13);
                const int kkl = kk & 3;
#pragma unroll
                for (int mt = 0; mt < 2; mt++) {
                    const int row = wm * 32 + mt * 16 + (lane & 15);
                    uint32_t ad = cur + sw(akh + (uint32_t)(row * 128 + kkl * 32 + (lane >> 4) * 16));
                    asm volatile("ldmatrix.sync.aligned.m8n8.x4.shared.b16 {%0,%1,%2,%3}, [%4];"
                                 : "=r"(a[hf][mt][0]), "=r"(a[hf][mt][1]),
                                   "=r"(a[hf][mt][2]), "=r"(a[hf][mt][3]) : "r"(ad));
                }
#pragma unroll
                for (int ntp = 0; ntp < 2; ntp++) {
                    const int row = wn * 32 + ntp * 16 + ((lane >> 4) & 1) * 8 + (lane & 7);
                    uint32_t ad = cur + A_BYTES + sw(bkh + (uint32_t)(row * 128 + kkl * 32 + ((lane >> 3) & 1) * 16));
                    asm volatile("ldmatrix.sync.aligned.m8n8.x4.shared.b16 {%0,%1,%2,%3}, [%4];"
                                 : "=r"(b[hf][2 * ntp][0]), "=r"(b[hf][2 * ntp][1]),
                                   "=r"(b[hf][2 * ntp + 1][0]), "=r"(b[hf][2 * ntp + 1][1]) : "r"(ad));
                }
            }
#pragma unroll
            for (int hf = 0; hf < 2; hf++)
#pragma unroll
                for (int mt = 0; mt < 2; mt++)
#pragma unroll
                    for (int nt = 0; nt < 4; nt++)
                        asm volatile("mma.sync.aligned.m16n8k16.row.col.f32.f16.f16.f32 "
                                     "{%0,%1,%2,%3}, {%4,%5,%6,%7}, {%8,%9}, {%0,%1,%2,%3};"
                                     : "+f"(c[mt][nt][0]), "+f"(c[mt][nt][1]), "+f"(c[mt][nt][2]), "+f"(c[mt][nt][3])
                                     : "r"(a[hf][mt][0]), "r"(a[hf][mt][1]), "r"(a[hf][mt][2]), "r"(a[hf][mt][3]),
                                       "r"(b[hf][nt][0]), "r"(b[hf][nt][1]));
        }

        if (produce)
            sts_fold_B(pbase + A_BYTES, pk, o_base, pch * 128, tid);  // own stores; visible via next bar
    }

    // epilogue: per-o scale in fp32, direct float2 stores
#pragma unroll
    for (int mt = 0; mt < 2; mt++) {
        const int m0 = wm * 32 + mt * 16 + (lane >> 2);
#pragma unroll
        for (int nt = 0; nt < 4; nt++) {
            const int o = o_base + wn * 32 + nt * 8 + (lane & 3) * 2;
            const float2 s = *reinterpret_cast<const float2*>(scales + o);
            float2 r0, r1;
            r0.x = c[mt][nt][0] * s.x; r0.y = c[mt][nt][1] * s.y;
            r1.x = c[mt][nt][2] * s.x; r1.y = c[mt][nt][3] * s.y;
            *reinterpret_cast<float2*>(out + (size_t)m0 * OO + o) = r0;
            *reinterpret_cast<float2*>(out + (size_t)(m0 + 8) * OO + o) = r1;
        }
    }
}

extern "C" void kernel_launch(void* const* d_in, const int* in_sizes, int n_in,
                              void* d_out, int out_size) {
    const float* x      = (const float*)d_in[0];
    const int*   packed = (const int*)d_in[1];
    const float* scales = (const float*)d_in[2];
    const void*  vals   = (const void*)d_in[3];
    const int*   idx    = (const int*)d_in[4];
    const int*   ptr    = (const int*)d_in[5];
    const float* alpha  = (const float*)d_in[6];
    float* out = (float*)d_out;

    cudaFuncSetAttribute(gemm_kernel, cudaFuncAttributeMaxDynamicSharedMemorySize, SMEM_BYTES);
    sniff_vals<<<1, 128>>>((const unsigned short*)vals);
    prep_kernel<<<2048 + OO, 256>>>(x, vals, idx, ptr, scales, alpha);
    gemm_kernel<<<128, 512, SMEM_BYTES>>>(packed, scales, out);
}